// round 6
// baseline (speedup 1.0000x reference)
#include <cuda_runtime.h>
#include <cstdint>

// ---------------- problem constants ----------------
#define T_    4
#define NBN   65536
#define P_    63
#define D_    128
#define M_    262144
#define TBND  8388608
#define NBLK  2048               // GEMM blocks, 128 rows each

// dyn smem: xt [63][132] floats (33264 B), ws [63][132] floats (33264 B)
#define XT_F   0
#define WS_F   8316              // float index of ws
#define SM_GEMM 66528

// ---------------- device globals ----------------
__device__ float  g_h[(size_t)M_ * D_];        // 134 MB intermediate h
__device__ float  g_wt[P_ * D_];               // W^T [p][d]
__device__ double g_psum[NBLK * D_];           // per-block channel sums (double)
__device__ double g_psq [NBLK * D_];
__device__ float  g_mean[D_];
__device__ float  g_rstd[D_];

// ---------------- packed fp32x2 helpers ----------------
__device__ __forceinline__ unsigned long long pk2(float a){
    unsigned long long r;
    asm("mov.b64 %0, {%1, %1};" : "=l"(r) : "f"(a));
    return r;
}
__device__ __forceinline__ void fma2(unsigned long long& d,
                                     unsigned long long a, unsigned long long b){
    asm("fma.rn.f32x2 %0, %1, %2, %0;" : "+l"(d) : "l"(a), "l"(b));
}
__device__ __forceinline__ float2 up2(unsigned long long v){
    float2 f;
    asm("mov.b64 {%0, %1}, %2;" : "=f"(f.x), "=f"(f.y) : "l"(v));
    return f;
}

// ---------------- K0: W [128][63] -> g_wt [63][128] ----------------
__global__ __launch_bounds__(256) void k_wt(const float* __restrict__ W){
    int idx = blockIdx.x * 256 + threadIdx.x;
    if (idx < P_ * D_){
        int p = idx >> 7;
        int d = idx & 127;
        g_wt[idx] = W[d * P_ + p];
    }
}

// ---------------- K1: fp32-sequential f32x2 GEMM (bit-identical to R1) ------
// 128 rows x 128 cols per block, 256 threads (16x16), thread tile 8x8.
// Each output element: acc = 0; for p = 0..62: acc = fma(x[m][p], W[d][p], acc)
// -- the exact chain that scored rel_err 0.0 in round 1.
__global__ __launch_bounds__(256, 2) void k_gemm(const float* __restrict__ x){
    extern __shared__ __align__(16) float smf[];
    float* xt = smf + XT_F;          // [63][132], xt[p*132 + r]
    float* ws = smf + WS_F;          // [63][132], ws[p*132 + d]
    const int tid = threadIdx.x;
    const int blk = blockIdx.x;

    // W^T copy: conflict-free (consecutive d)
    #pragma unroll
    for (int i = tid; i < P_ * D_; i += 256){
        int p = i >> 7;
        int d = i & 127;
        ws[p * 132 + d] = g_wt[i];
    }
    // x tile transpose: coalesced read, 4-way-conflict writes (once)
    {
        const float* xg = x + (size_t)blk * (128 * P_);
        #pragma unroll
        for (int i = tid; i < 128 * P_; i += 256){
            int r = i / P_;
            int p = i - r * P_;
            xt[p * 132 + r] = xg[i];
        }
    }
    __syncthreads();

    const int tx = tid & 15;         // col group: cols tx*8 .. +7
    const int ty = tid >> 4;         // row group: rows ty*8 .. +7

    unsigned long long acc[4][8];    // [row-pair][col], lane.lo = even row
    #pragma unroll
    for (int rp = 0; rp < 4; rp++)
        #pragma unroll
        for (int c = 0; c < 8; c++) acc[rp][c] = 0ull;

    const float* xb = xt + ty * 8;
    const float* wb = ws + tx * 8;

    #pragma unroll 3
    for (int p = 0; p < P_; p++){
        const float* xr = xb + p * 132;
        unsigned long long xa0 = *(const unsigned long long*)(xr + 0);
        unsigned long long xa1 = *(const unsigned long long*)(xr + 2);
        unsigned long long xa2 = *(const unsigned long long*)(xr + 4);
        unsigned long long xa3 = *(const unsigned long long*)(xr + 6);
        const float4* wq = (const float4*)(wb + p * 132);
        float4 w0 = wq[0];
        float4 w1 = wq[1];
        unsigned long long d0 = pk2(w0.x), d1 = pk2(w0.y), d2 = pk2(w0.z), d3 = pk2(w0.w);
        unsigned long long d4 = pk2(w1.x), d5 = pk2(w1.y), d6 = pk2(w1.z), d7 = pk2(w1.w);
        fma2(acc[0][0], xa0, d0); fma2(acc[1][0], xa1, d0);
        fma2(acc[2][0], xa2, d0); fma2(acc[3][0], xa3, d0);
        fma2(acc[0][1], xa0, d1); fma2(acc[1][1], xa1, d1);
        fma2(acc[2][1], xa2, d1); fma2(acc[3][1], xa3, d1);
        fma2(acc[0][2], xa0, d2); fma2(acc[1][2], xa1, d2);
        fma2(acc[2][2], xa2, d2); fma2(acc[3][2], xa3, d2);
        fma2(acc[0][3], xa0, d3); fma2(acc[1][3], xa1, d3);
        fma2(acc[2][3], xa2, d3); fma2(acc[3][3], xa3, d3);
        fma2(acc[0][4], xa0, d4); fma2(acc[1][4], xa1, d4);
        fma2(acc[2][4], xa2, d4); fma2(acc[3][4], xa3, d4);
        fma2(acc[0][5], xa0, d5); fma2(acc[1][5], xa1, d5);
        fma2(acc[2][5], xa2, d5); fma2(acc[3][5], xa3, d5);
        fma2(acc[0][6], xa0, d6); fma2(acc[1][6], xa1, d6);
        fma2(acc[2][6], xa2, d6); fma2(acc[3][6], xa3, d6);
        fma2(acc[0][7], xa0, d7); fma2(acc[1][7], xa1, d7);
        fma2(acc[2][7], xa2, d7); fma2(acc[3][7], xa3, d7);
    }

    __syncthreads();    // all smem reads done; safe to reuse for stats

    // h write: 2 x STG.128 per row, 8 rows (256B-coalesced per warp-row)
    float* hg = g_h + (size_t)blk * (128 * 128) + tx * 8;
    #pragma unroll
    for (int rp = 0; rp < 4; rp++){
        float2 c0 = up2(acc[rp][0]), c1 = up2(acc[rp][1]);
        float2 c2 = up2(acc[rp][2]), c3 = up2(acc[rp][3]);
        float2 c4 = up2(acc[rp][4]), c5 = up2(acc[rp][5]);
        float2 c6 = up2(acc[rp][6]), c7 = up2(acc[rp][7]);
        float* r0 = hg + (ty * 8 + rp * 2) * 128;
        float* r1 = r0 + 128;
        *(float4*)(r0)     = make_float4(c0.x, c1.x, c2.x, c3.x);
        *(float4*)(r0 + 4) = make_float4(c4.x, c5.x, c6.x, c7.x);
        *(float4*)(r1)     = make_float4(c0.y, c1.y, c2.y, c3.y);
        *(float4*)(r1 + 4) = make_float4(c4.y, c5.y, c6.y, c7.y);
    }

    // stats: per-thread 8-row col sums in double, block-reduce over ty
    double* sdA = (double*)smf;              // [16][128]
    double* sdB = sdA + 16 * 128;            // [16][128]
    #pragma unroll
    for (int c = 0; c < 8; c++){
        double s = 0.0, q = 0.0;
        #pragma unroll
        for (int rp = 0; rp < 4; rp++){
            float2 f = up2(acc[rp][c]);
            s += (double)f.x + (double)f.y;
            q += (double)f.x * (double)f.x + (double)f.y * (double)f.y;
        }
        sdA[ty * 128 + tx * 8 + c] = s;
        sdB[ty * 128 + tx * 8 + c] = q;
    }
    __syncthreads();
    if (tid < 128){
        double s = 0.0, q = 0.0;
        #pragma unroll
        for (int r = 0; r < 16; r++){
            s += sdA[r * 128 + tid];
            q += sdB[r * 128 + tid];
        }
        g_psum[blk * D_ + tid] = s;
        g_psq [blk * D_ + tid] = q;
    }
}

// ---------------- K2: finalize stats (double), fold gamma/beta --------------
__global__ __launch_bounds__(256) void k_stats(const float* __restrict__ gamma,
                                               const float* __restrict__ beta){
    __shared__ double ss[256];
    __shared__ double sq[256];
    const int d = blockIdx.x;
    const int t = threadIdx.x;
    double s = 0.0, q = 0.0;
    for (int b = t; b < NBLK; b += 256){
        s += g_psum[b * D_ + d];
        q += g_psq [b * D_ + d];
    }
    ss[t] = s; sq[t] = q;
    __syncthreads();
    for (int o = 128; o > 0; o >>= 1){
        if (t < o){ ss[t] += ss[t + o]; sq[t] += sq[t + o]; }
        __syncthreads();
    }
    if (t == 0){
        double mean = ss[0] / (double)M_;
        double ex2  = sq[0] / (double)M_;
        float meanf = (float)mean;
        float varf  = (float)(ex2 - mean * mean);
        float rstd  = (float)(1.0 / sqrt((double)(varf + 1e-5f)));
        float gm = gamma[d], bt = beta[d];
        float rs = rstd * gm;
        float mn = (rs != 0.f) ? (meanf - bt / rs) : meanf;   // exact for gm=1,bt=0
        g_mean[d] = mn;
        g_rstd[d] = rs;
    }
}

// ---------------- K3: BN + 4-step LIF (identical to round 1) ----------------
__global__ __launch_bounds__(256) void k_lif(float* __restrict__ out){
    int i = blockIdx.x * 256 + threadIdx.x;
    int d0 = (i << 2) & 127;
    float4 mn = *(const float4*)(g_mean + d0);
    float4 rs = *(const float4*)(g_rstd + d0);
    size_t base = (size_t)i << 2;

    float v0 = 0.f, v1 = 0.f, v2 = 0.f, v3 = 0.f;
    #pragma unroll
    for (int t = 0; t < 4; t++){
        float4 h = *(const float4*)(g_h + base + (size_t)t * TBND);
        float n0 = (h.x - mn.x) * rs.x;
        float n1 = (h.y - mn.y) * rs.y;
        float n2 = (h.z - mn.z) * rs.z;
        float n3 = (h.w - mn.w) * rs.w;
        v0 = v0 + (n0 - v0) * 0.5f;
        v1 = v1 + (n1 - v1) * 0.5f;
        v2 = v2 + (n2 - v2) * 0.5f;
        v3 = v3 + (n3 - v3) * 0.5f;
        float4 o;
        o.x = (v0 >= 1.0f) ? 1.0f : 0.0f;
        o.y = (v1 >= 1.0f) ? 1.0f : 0.0f;
        o.z = (v2 >= 1.0f) ? 1.0f : 0.0f;
        o.w = (v3 >= 1.0f) ? 1.0f : 0.0f;
        if (v0 >= 1.0f) v0 = 0.f;
        if (v1 >= 1.0f) v1 = 0.f;
        if (v2 >= 1.0f) v2 = 0.f;
        if (v3 >= 1.0f) v3 = 0.f;
        *(float4*)(out + base + (size_t)t * TBND) = o;
    }
}

// ---------------- launch ----------------
extern "C" void kernel_launch(void* const* d_in, const int* in_sizes, int n_in,
                              void* d_out, int out_size){
    const float* x     = (const float*)d_in[0];
    const float* W     = (const float*)d_in[1];
    const float* gamma = (const float*)d_in[2];
    const float* beta  = (const float*)d_in[3];
    float* out = (float*)d_out;

    cudaFuncSetAttribute(k_gemm, cudaFuncAttributeMaxDynamicSharedMemorySize, SM_GEMM);

    k_wt   <<<32, 256>>>(W);
    k_gemm <<<NBLK, 256, SM_GEMM>>>(x);
    k_stats<<<D_, 256>>>(gamma, beta);
    k_lif  <<<TBND / 4 / 256, 256>>>(out);
}